// round 14
// baseline (speedup 1.0000x reference)
#include <cuda_runtime.h>

#define BB 32
#define HW 307200           // 480*640
#define HW4 76800           // float4 per plane
#define EPS 1e-5
#define NQ (BB * HW4)       // 2,457,600 quads total
#define THREADS 1024
#define KEEP_IT 4           // retained iterations/thread: 4*1024*48B = 192KB
#define SMEM_QUADS (KEEP_IT * THREADS)           // 4096 triples
#define SMEM_BYTES (3 * SMEM_QUADS * 16)         // 196608

#define MAX_CTAS 512

__device__ float g_partials[MAX_CTAS * 9];
__device__ unsigned g_arrive;
__device__ unsigned g_depart;

__device__ __forceinline__ void accum9(float* __restrict__ s,
                                       const float4& x0, const float4& x1, const float4& x2) {
    s[0] += x0.x + x0.y + x0.z + x0.w;
    s[1] += x1.x + x1.y + x1.z + x1.w;
    s[2] += x2.x + x2.y + x2.z + x2.w;
    s[3] += x0.x*x0.x + x0.y*x0.y + x0.z*x0.z + x0.w*x0.w;
    s[4] += x0.x*x1.x + x0.y*x1.y + x0.z*x1.z + x0.w*x1.w;
    s[5] += x0.x*x2.x + x0.y*x2.y + x0.z*x2.z + x0.w*x2.w;
    s[6] += x1.x*x1.x + x1.y*x1.y + x1.z*x1.z + x1.w*x1.w;
    s[7] += x1.x*x2.x + x1.y*x2.y + x1.z*x2.z + x1.w*x2.w;
    s[8] += x2.x*x2.x + x2.y*x2.y + x2.z*x2.z + x2.w*x2.w;
}

__global__ void __launch_bounds__(THREADS, 1) fused_kernel(
    const float4* __restrict__ X, float4* __restrict__ OUT,
    const float* __restrict__ w1, const float* __restrict__ b1,
    const float* __restrict__ g2, const float* __restrict__ be2,
    const float* __restrict__ w3, const float* __restrict__ b3,
    const float* __restrict__ w4, const float* __restrict__ b4,
    const float* __restrict__ g5, const float* __restrict__ be5,
    const float* __restrict__ w6, const float* __restrict__ b6,
    const float* __restrict__ w7, const float* __restrict__ b7,
    const float* __restrict__ w8, const float* __restrict__ b8)
{
    extern __shared__ float4 s_x[];          // [3][SMEM_QUADS]
    __shared__ float sh[THREADS / 32][9];
    __shared__ double sums[9];
    __shared__ float sAc[32];                // A[8][3] then c[8]

    const int grid = gridDim.x;
    const int cta  = blockIdx.x;
    const int tid  = threadIdx.x;

    const int Q  = (NQ + grid - 1) / grid;
    const int q0 = cta * Q;
    const int q1 = (q0 + Q < NQ) ? (q0 + Q) : NQ;
    const int len = q1 - q0;
    const int nit = (tid < len) ? ((len - tid + THREADS - 1) / THREADS) : 0;

    // ---------------- Phase 1: moments (+ retain first KEEP_IT iters) -------
    float s[9];
#pragma unroll
    for (int j = 0; j < 9; j++) s[j] = 0.f;
    {
        int l = q0 + tid;
        int b = l / HW4;
        int p = l - b * HW4;
        for (int i = 0; i < nit; i++) {
            const float4* base = X + (size_t)b * 3 * HW4 + p;
            float4 x0 = __ldcg(base);
            float4 x1 = __ldcg(base + HW4);
            float4 x2 = __ldcg(base + 2 * HW4);
            if (i < KEEP_IT) {
                int j = i * THREADS + tid;
                s_x[j] = x0;
                s_x[SMEM_QUADS + j] = x1;
                s_x[2 * SMEM_QUADS + j] = x2;
            }
            accum9(s, x0, x1, x2);
            p += THREADS;
            if (p >= HW4) { p -= HW4; b++; }
        }
    }
#pragma unroll
    for (int j = 0; j < 9; j++)
#pragma unroll
        for (int off = 16; off > 0; off >>= 1)
            s[j] += __shfl_down_sync(0xffffffffu, s[j], off);
    {
        const int lane = tid & 31, warp = tid >> 5;
        if (lane == 0) {
#pragma unroll
            for (int j = 0; j < 9; j++) sh[warp][j] = s[j];
        }
    }
    __syncthreads();
    if (tid == 0) {
        float t[9];
#pragma unroll
        for (int j = 0; j < 9; j++) t[j] = 0.f;
        for (int w = 0; w < THREADS / 32; w++)
#pragma unroll
            for (int j = 0; j < 9; j++) t[j] += sh[w][j];
#pragma unroll
        for (int j = 0; j < 9; j++) g_partials[cta * 9 + j] = t[j];
        __threadfence();                       // release partials
        atomicAdd(&g_arrive, 1);
        while (atomicAdd(&g_arrive, 0) < (unsigned)grid) __nanosleep(128);
    }
    __syncthreads();
    __threadfence();                           // acquire all partials

    // ---------------- Fold network into A, c (redundant per CTA) ------------
    {
        const int warp = tid >> 5, lane = tid & 31;
        if (warp < 9) {
            double acc = 0.0;
            for (int i = lane; i < grid; i += 32)
                acc += (double)g_partials[i * 9 + warp];
#pragma unroll
            for (int off = 16; off > 0; off >>= 1)
                acc += __shfl_down_sync(0xffffffffu, acc, off);
            if (lane == 0) sums[warp] = acc;
        }
    }
    __syncthreads();
    if (tid == 0) {
        const double N = (double)BB * (double)HW;
        double m[3];
        for (int k = 0; k < 3; k++) m[k] = sums[k] / N;
        double E[3][3];
        E[0][0] = sums[3]/N; E[0][1] = E[1][0] = sums[4]/N; E[0][2] = E[2][0] = sums[5]/N;
        E[1][1] = sums[6]/N; E[1][2] = E[2][1] = sums[7]/N; E[2][2] = sums[8]/N;
        double Cov[3][3];
        for (int k = 0; k < 3; k++)
            for (int d = 0; d < 3; d++)
                Cov[k][d] = E[k][d] - m[k] * m[d];

        double M[8][3], c[8], Mn[8][3], cn[8];
        for (int r = 0; r < 3; r++) {
            for (int k = 0; k < 3; k++) M[r][k] = (double)w1[r * 3 + k];
            c[r] = (double)b1[r];
        }
        for (int r = 0; r < 3; r++) {          // BN2
            double mean = c[r];
            for (int k = 0; k < 3; k++) mean += M[r][k] * m[k];
            double var = 0.0;
            for (int k = 0; k < 3; k++)
                for (int d = 0; d < 3; d++)
                    var += M[r][k] * Cov[k][d] * M[r][d];
            double sc = (double)g2[r] / sqrt(var + EPS);
            for (int k = 0; k < 3; k++) M[r][k] *= sc;
            c[r] = sc * (c[r] - mean) + (double)be2[r];
        }
        for (int o = 0; o < 8; o++) {          // conv w3 [8,3]
            for (int k = 0; k < 3; k++) {
                double a = 0.0;
                for (int r = 0; r < 3; r++) a += (double)w3[o * 3 + r] * M[r][k];
                Mn[o][k] = a;
            }
            double a = (double)b3[o];
            for (int r = 0; r < 3; r++) a += (double)w3[o * 3 + r] * c[r];
            cn[o] = a;
        }
        for (int o = 0; o < 8; o++) { for (int k = 0; k < 3; k++) M[o][k] = Mn[o][k]; c[o] = cn[o]; }
        for (int o = 0; o < 8; o++) {          // conv w4 [8,8]
            for (int k = 0; k < 3; k++) {
                double a = 0.0;
                for (int r = 0; r < 8; r++) a += (double)w4[o * 8 + r] * M[r][k];
                Mn[o][k] = a;
            }
            double a = (double)b4[o];
            for (int r = 0; r < 8; r++) a += (double)w4[o * 8 + r] * c[r];
            cn[o] = a;
        }
        for (int o = 0; o < 8; o++) { for (int k = 0; k < 3; k++) M[o][k] = Mn[o][k]; c[o] = cn[o]; }
        for (int o = 0; o < 8; o++) {          // BN5
            double mean = c[o];
            for (int k = 0; k < 3; k++) mean += M[o][k] * m[k];
            double var = 0.0;
            for (int k = 0; k < 3; k++)
                for (int d = 0; d < 3; d++)
                    var += M[o][k] * Cov[k][d] * M[o][d];
            double sc = (double)g5[o] / sqrt(var + EPS);
            for (int k = 0; k < 3; k++) M[o][k] *= sc;
            c[o] = sc * (c[o] - mean) + (double)be5[o];
        }
        const float* Ws[3] = { w6, w7, w8 };
        const float* Bs[3] = { b6, b7, b8 };
        for (int L = 0; L < 3; L++) {
            const float* Wl = Ws[L];
            const float* Bl = Bs[L];
            for (int o = 0; o < 8; o++) {
                for (int k = 0; k < 3; k++) {
                    double a = 0.0;
                    for (int r = 0; r < 8; r++) a += (double)Wl[o * 8 + r] * M[r][k];
                    Mn[o][k] = a;
                }
                double a = (double)Bl[o];
                for (int r = 0; r < 8; r++) a += (double)Wl[o * 8 + r] * c[r];
                cn[o] = a;
            }
            for (int o = 0; o < 8; o++) { for (int k = 0; k < 3; k++) M[o][k] = Mn[o][k]; c[o] = cn[o]; }
        }
        for (int o = 0; o < 8; o++) {
            for (int k = 0; k < 3; k++) sAc[o * 3 + k] = (float)M[o][k];
            sAc[24 + o] = (float)c[o];
        }
    }
    __syncthreads();

    float a0[8], a1[8], a2[8], cc[8];
#pragma unroll
    for (int o = 0; o < 8; o++) {
        a0[o] = sAc[o * 3 + 0];
        a1[o] = sAc[o * 3 + 1];
        a2[o] = sAc[o * 3 + 2];
        cc[o] = sAc[24 + o];
    }

    // ---------------- Phase 2: out = A x + c --------------------------------
    // Non-retained iterations first, most-recently-read-first (L2 harvest),
    // then retained ones from smem.
    for (int i = nit - 1; i >= 0; i--) {
        const int l = q0 + tid + i * THREADS;
        const int b = l / HW4;
        const int p = l - b * HW4;
        float4 x0, x1, x2;
        if (i < KEEP_IT) {
            const int j = i * THREADS + tid;
            x0 = s_x[j];
            x1 = s_x[SMEM_QUADS + j];
            x2 = s_x[2 * SMEM_QUADS + j];
        } else {
            const float4* base = X + (size_t)b * 3 * HW4 + p;
            x0 = __ldcg(base);
            x1 = __ldcg(base + HW4);
            x2 = __ldcg(base + 2 * HW4);
        }
        float4* ob = OUT + (size_t)b * 8 * HW4 + p;
#pragma unroll
        for (int o = 0; o < 8; o++) {
            float4 r;
            r.x = fmaf(a0[o], x0.x, fmaf(a1[o], x1.x, fmaf(a2[o], x2.x, cc[o])));
            r.y = fmaf(a0[o], x0.y, fmaf(a1[o], x1.y, fmaf(a2[o], x2.y, cc[o])));
            r.z = fmaf(a0[o], x0.z, fmaf(a1[o], x1.z, fmaf(a2[o], x2.z, cc[o])));
            r.w = fmaf(a0[o], x0.w, fmaf(a1[o], x1.w, fmaf(a2[o], x2.w, cc[o])));
            __stcs(ob + o * HW4, r);
        }
    }

    // ---------------- Barrier reset (graph-replay safe) ---------------------
    __syncthreads();
    if (tid == 0) {
        unsigned t = atomicAdd(&g_depart, 1);
        if (t == (unsigned)(grid - 1)) {
            g_arrive = 0;
            g_depart = 0;
            __threadfence();
        }
    }
}

extern "C" void kernel_launch(void* const* d_in, const int* in_sizes, int n_in,
                              void* d_out, int out_size) {
    const float* x1  = (const float*)d_in[0];
    const float* w1  = (const float*)d_in[1];
    const float* b1  = (const float*)d_in[2];
    const float* g2  = (const float*)d_in[3];
    const float* be2 = (const float*)d_in[4];
    const float* w3  = (const float*)d_in[5];
    const float* b3  = (const float*)d_in[6];
    const float* w4  = (const float*)d_in[7];
    const float* b4  = (const float*)d_in[8];
    const float* g5  = (const float*)d_in[9];
    const float* be5 = (const float*)d_in[10];
    const float* w6  = (const float*)d_in[11];
    const float* b6  = (const float*)d_in[12];
    const float* w7  = (const float*)d_in[13];
    const float* b7  = (const float*)d_in[14];
    const float* w8  = (const float*)d_in[15];
    const float* b8  = (const float*)d_in[16];

    int dev = 0;
    cudaGetDevice(&dev);
    int nsm = 148;
    cudaDeviceGetAttribute(&nsm, cudaDevAttrMultiProcessorCount, dev);
    if (nsm > MAX_CTAS) nsm = MAX_CTAS;
    if (nsm < 1) nsm = 1;

    cudaFuncSetAttribute(fused_kernel,
                         cudaFuncAttributeMaxDynamicSharedMemorySize, SMEM_BYTES);

    fused_kernel<<<nsm, THREADS, SMEM_BYTES>>>(
        (const float4*)x1, (float4*)d_out,
        w1, b1, g2, be2, w3, b3, w4, b4,
        g5, be5, w6, b6, w7, b7, w8, b8);
}

// round 15
// speedup vs baseline: 1.0733x; 1.0733x over previous
#include <cuda_runtime.h>

#define BB 32
#define HH 480
#define WW 640
#define HW (HH*WW)          // 307200
#define HW4 (HW/4)          // 76800 float4 per plane
#define EPS 1e-5

// reduce: grid (RED_GX, BB) x 256 threads; HW4 = 6 * RED_GX * 256 exactly
#define RED_GX 25
#define RED_THREADS 256
#define RED_STRIDE (RED_GX * RED_THREADS)    // 6400
#define RED_ITERS (HW4 / RED_STRIDE)         // 12? no: 76800/6400 = 12
#define RED_BLOCKS (RED_GX * BB)             // 800

// apply: grid (APL_GX, BB) x 256 threads, 4 quads per thread
#define APL_GX 75                            // 75 * 1024 = 76800 (exact)

__device__ float g_partials[RED_BLOCKS * 9];
__device__ float g_A[8 * 3];
__device__ float g_c[8];
__device__ unsigned g_done;                  // last-block-done counter

__device__ __forceinline__ void accum9(float* __restrict__ s,
                                       const float4& x0, const float4& x1, const float4& x2) {
    s[0] += x0.x + x0.y + x0.z + x0.w;
    s[1] += x1.x + x1.y + x1.z + x1.w;
    s[2] += x2.x + x2.y + x2.z + x2.w;
    s[3] += x0.x*x0.x + x0.y*x0.y + x0.z*x0.z + x0.w*x0.w;
    s[4] += x0.x*x1.x + x0.y*x1.y + x0.z*x1.z + x0.w*x1.w;
    s[5] += x0.x*x2.x + x0.y*x2.y + x0.z*x2.z + x0.w*x2.w;
    s[6] += x1.x*x1.x + x1.y*x1.y + x1.z*x1.z + x1.w*x1.w;
    s[7] += x1.x*x2.x + x1.y*x2.y + x1.z*x2.z + x1.w*x2.w;
    s[8] += x2.x*x2.x + x2.y*x2.y + x2.z*x2.z + x2.w*x2.w;
}

// Fold the whole network into A[8][3], c[8] given the 9 global sums.
__device__ void fold_network(const double* sums,
    const float* w1, const float* b1, const float* g2, const float* be2,
    const float* w3, const float* b3, const float* w4, const float* b4,
    const float* g5, const float* be5, const float* w6, const float* b6,
    const float* w7, const float* b7, const float* w8, const float* b8)
{
    const double N = (double)BB * (double)HW;
    double m[3];
    for (int k = 0; k < 3; k++) m[k] = sums[k] / N;
    double E[3][3];
    E[0][0] = sums[3]/N; E[0][1] = E[1][0] = sums[4]/N; E[0][2] = E[2][0] = sums[5]/N;
    E[1][1] = sums[6]/N; E[1][2] = E[2][1] = sums[7]/N; E[2][2] = sums[8]/N;
    double Cov[3][3];
    for (int k = 0; k < 3; k++)
        for (int d = 0; d < 3; d++)
            Cov[k][d] = E[k][d] - m[k] * m[d];

    double M[8][3], c[8], Mn[8][3], cn[8];
    for (int r = 0; r < 3; r++) {
        for (int k = 0; k < 3; k++) M[r][k] = (double)w1[r * 3 + k];
        c[r] = (double)b1[r];
    }
    for (int r = 0; r < 3; r++) {               // BN2
        double mean = c[r];
        for (int k = 0; k < 3; k++) mean += M[r][k] * m[k];
        double var = 0.0;
        for (int k = 0; k < 3; k++)
            for (int d = 0; d < 3; d++)
                var += M[r][k] * Cov[k][d] * M[r][d];
        double sc = (double)g2[r] / sqrt(var + EPS);
        for (int k = 0; k < 3; k++) M[r][k] *= sc;
        c[r] = sc * (c[r] - mean) + (double)be2[r];
    }
    for (int o = 0; o < 8; o++) {               // conv w3 [8,3]
        for (int k = 0; k < 3; k++) {
            double a = 0.0;
            for (int r = 0; r < 3; r++) a += (double)w3[o * 3 + r] * M[r][k];
            Mn[o][k] = a;
        }
        double a = (double)b3[o];
        for (int r = 0; r < 3; r++) a += (double)w3[o * 3 + r] * c[r];
        cn[o] = a;
    }
    for (int o = 0; o < 8; o++) { for (int k = 0; k < 3; k++) M[o][k] = Mn[o][k]; c[o] = cn[o]; }
    for (int o = 0; o < 8; o++) {               // conv w4 [8,8]
        for (int k = 0; k < 3; k++) {
            double a = 0.0;
            for (int r = 0; r < 8; r++) a += (double)w4[o * 8 + r] * M[r][k];
            Mn[o][k] = a;
        }
        double a = (double)b4[o];
        for (int r = 0; r < 8; r++) a += (double)w4[o * 8 + r] * c[r];
        cn[o] = a;
    }
    for (int o = 0; o < 8; o++) { for (int k = 0; k < 3; k++) M[o][k] = Mn[o][k]; c[o] = cn[o]; }
    for (int o = 0; o < 8; o++) {               // BN5
        double mean = c[o];
        for (int k = 0; k < 3; k++) mean += M[o][k] * m[k];
        double var = 0.0;
        for (int k = 0; k < 3; k++)
            for (int d = 0; d < 3; d++)
                var += M[o][k] * Cov[k][d] * M[o][d];
        double sc = (double)g5[o] / sqrt(var + EPS);
        for (int k = 0; k < 3; k++) M[o][k] *= sc;
        c[o] = sc * (c[o] - mean) + (double)be5[o];
    }
    const float* Ws[3] = { w6, w7, w8 };
    const float* Bs[3] = { b6, b7, b8 };
    for (int L = 0; L < 3; L++) {
        const float* Wl = Ws[L];
        const float* Bl = Bs[L];
        for (int o = 0; o < 8; o++) {
            for (int k = 0; k < 3; k++) {
                double a = 0.0;
                for (int r = 0; r < 8; r++) a += (double)Wl[o * 8 + r] * M[r][k];
                Mn[o][k] = a;
            }
            double a = (double)Bl[o];
            for (int r = 0; r < 8; r++) a += (double)Wl[o * 8 + r] * c[r];
            cn[o] = a;
        }
        for (int o = 0; o < 8; o++) { for (int k = 0; k < 3; k++) M[o][k] = Mn[o][k]; c[o] = cn[o]; }
    }
    for (int o = 0; o < 8; o++) {
        for (int k = 0; k < 3; k++) g_A[o * 3 + k] = (float)M[o][k];
        g_c[o] = (float)c[o];
    }
}

// ---------------------------------------------------------------------------
// Pass 1: moment reduction + last-block fold (removes the finalize launch).
// ---------------------------------------------------------------------------
__global__ void __launch_bounds__(RED_THREADS) reduce_kernel(
    const float4* __restrict__ X,
    const float* __restrict__ w1, const float* __restrict__ b1,
    const float* __restrict__ g2, const float* __restrict__ be2,
    const float* __restrict__ w3, const float* __restrict__ b3,
    const float* __restrict__ w4, const float* __restrict__ b4,
    const float* __restrict__ g5, const float* __restrict__ be5,
    const float* __restrict__ w6, const float* __restrict__ b6,
    const float* __restrict__ w7, const float* __restrict__ b7,
    const float* __restrict__ w8, const float* __restrict__ b8)
{
    float s[9];
#pragma unroll
    for (int j = 0; j < 9; j++) s[j] = 0.f;

    const float4* base = X + (size_t)blockIdx.y * 3 * HW4;
    int p = blockIdx.x * RED_THREADS + threadIdx.x;

#pragma unroll 2
    for (int it = 0; it < RED_ITERS; it += 2) {
        float4 x0a = base[p];
        float4 x1a = base[p + HW4];
        float4 x2a = base[p + 2*HW4];
        float4 x0b = base[p + RED_STRIDE];
        float4 x1b = base[p + RED_STRIDE + HW4];
        float4 x2b = base[p + RED_STRIDE + 2*HW4];
        p += 2 * RED_STRIDE;
        accum9(s, x0a, x1a, x2a);
        accum9(s, x0b, x1b, x2b);
    }

#pragma unroll
    for (int j = 0; j < 9; j++)
#pragma unroll
        for (int off = 16; off > 0; off >>= 1)
            s[j] += __shfl_down_sync(0xffffffffu, s[j], off);

    __shared__ float sh[RED_THREADS / 32][9];
    __shared__ bool s_last;
    const int lane = threadIdx.x & 31;
    const int warp = threadIdx.x >> 5;
    if (lane == 0) {
#pragma unroll
        for (int j = 0; j < 9; j++) sh[warp][j] = s[j];
    }
    __syncthreads();
    if (threadIdx.x == 0) {
        float t[9];
#pragma unroll
        for (int j = 0; j < 9; j++) t[j] = 0.f;
        for (int w = 0; w < RED_THREADS / 32; w++)
#pragma unroll
            for (int j = 0; j < 9; j++) t[j] += sh[w][j];
        const int bid = blockIdx.y * RED_GX + blockIdx.x;
#pragma unroll
        for (int j = 0; j < 9; j++) g_partials[bid * 9 + j] = t[j];
        __threadfence();                                   // release partials
        unsigned n = atomicAdd(&g_done, 1);
        s_last = (n == (unsigned)(RED_BLOCKS - 1));
        if (s_last) g_done = 0;                            // reset for graph replay
    }
    __syncthreads();
    if (!s_last) return;

    // ---- last block: global partial sum (fixed order) + network fold ----
    __threadfence();                                       // acquire all partials
    __shared__ double sums[9];
    // warp w reduces moment w; warp 0 additionally does moment 8.
    if (warp < 8) {
        double acc = 0.0;
        for (int i = lane; i < RED_BLOCKS; i += 32)
            acc += (double)g_partials[i * 9 + warp];
#pragma unroll
        for (int off = 16; off > 0; off >>= 1)
            acc += __shfl_down_sync(0xffffffffu, acc, off);
        if (lane == 0) sums[warp] = acc;
    }
    if (warp == 0) {
        double acc = 0.0;
        for (int i = lane; i < RED_BLOCKS; i += 32)
            acc += (double)g_partials[i * 9 + 8];
#pragma unroll
        for (int off = 16; off > 0; off >>= 1)
            acc += __shfl_down_sync(0xffffffffu, acc, off);
        if (lane == 0) sums[8] = acc;
    }
    __syncthreads();
    if (threadIdx.x == 0) {
        double ls[9];
#pragma unroll
        for (int j = 0; j < 9; j++) ls[j] = sums[j];
        fold_network(ls, w1, b1, g2, be2, w3, b3, w4, b4,
                     g5, be5, w6, b6, w7, b7, w8, b8);
        __threadfence();                                   // release A, c
    }
}

// ---------------------------------------------------------------------------
// Pass 2: out = A x + c.  4 quads/thread, 12 front-batched loads,
// streaming stores.  (Proven 106.5 µs configuration.)
// ---------------------------------------------------------------------------
__global__ void __launch_bounds__(256) apply_kernel(const float4* __restrict__ X,
                                                    float4* __restrict__ OUT) {
    const int b  = (BB - 1) - blockIdx.y;
    const int rb = (APL_GX - 1) - blockIdx.x;
    const int p0 = rb * 1024 + threadIdx.x;

    float a0[8], a1[8], a2[8], cc[8];
#pragma unroll
    for (int o = 0; o < 8; o++) {
        a0[o] = g_A[o * 3 + 0];
        a1[o] = g_A[o * 3 + 1];
        a2[o] = g_A[o * 3 + 2];
        cc[o] = g_c[o];
    }

    const float4* base = X + (size_t)b * 3 * HW4;
    float4 x0[4], x1[4], x2[4];
#pragma unroll
    for (int q = 0; q < 4; q++) {
        int p = p0 + q * 256;
        x0[q] = __ldcg(base + p);
        x1[q] = __ldcg(base + p + HW4);
        x2[q] = __ldcg(base + p + 2 * HW4);
    }

    float4* ob = OUT + (size_t)b * 8 * HW4;
#pragma unroll
    for (int o = 0; o < 8; o++) {
        float4* op = ob + o * HW4 + p0;
#pragma unroll
        for (int q = 0; q < 4; q++) {
            float4 r;
            r.x = fmaf(a0[o], x0[q].x, fmaf(a1[o], x1[q].x, fmaf(a2[o], x2[q].x, cc[o])));
            r.y = fmaf(a0[o], x0[q].y, fmaf(a1[o], x1[q].y, fmaf(a2[o], x2[q].y, cc[o])));
            r.z = fmaf(a0[o], x0[q].z, fmaf(a1[o], x1[q].z, fmaf(a2[o], x2[q].z, cc[o])));
            r.w = fmaf(a0[o], x0[q].w, fmaf(a1[o], x1[q].w, fmaf(a2[o], x2[q].w, cc[o])));
            __stcs(op + q * 256, r);
        }
    }
}

extern "C" void kernel_launch(void* const* d_in, const int* in_sizes, int n_in,
                              void* d_out, int out_size) {
    const float* x1  = (const float*)d_in[0];
    const float* w1  = (const float*)d_in[1];
    const float* b1  = (const float*)d_in[2];
    const float* g2  = (const float*)d_in[3];
    const float* be2 = (const float*)d_in[4];
    const float* w3  = (const float*)d_in[5];
    const float* b3  = (const float*)d_in[6];
    const float* w4  = (const float*)d_in[7];
    const float* b4  = (const float*)d_in[8];
    const float* g5  = (const float*)d_in[9];
    const float* be5 = (const float*)d_in[10];
    const float* w6  = (const float*)d_in[11];
    const float* b6  = (const float*)d_in[12];
    const float* w7  = (const float*)d_in[13];
    const float* b7  = (const float*)d_in[14];
    const float* w8  = (const float*)d_in[15];
    const float* b8  = (const float*)d_in[16];

    reduce_kernel<<<dim3(RED_GX, BB), RED_THREADS>>>(
        (const float4*)x1, w1, b1, g2, be2, w3, b3, w4, b4,
        g5, be5, w6, b6, w7, b7, w8, b8);
    apply_kernel<<<dim3(APL_GX, BB), 256>>>((const float4*)x1, (float4*)d_out);
}

// round 17
// speedup vs baseline: 1.1254x; 1.0486x over previous
#include <cuda_runtime.h>

#define BB 32
#define HH 480
#define WW 640
#define HW (HH*WW)          // 307200
#define HW4 (HW/4)          // 76800 float4 per plane
#define EPS 1e-5

// reduce: grid (RED_GX, BB) x 256 threads (best measured: 22.1us)
#define RED_GX 25
#define RED_THREADS 256
#define RED_BLOCKS (RED_GX * BB)             // 800

// apply: grid (APL_GX, BB) x 256 threads, 4 quads per thread
#define APL_GX 75                            // 75 * 1024 = 76800 (exact)

__device__ float g_partials[RED_BLOCKS * 9];
__device__ __align__(16) float g_Ac[8][4];   // per channel: a0,a1,a2,c (16B)

// un-hoistable 16B coefficient load (L1-resident after first touch)
__device__ __forceinline__ float4 ldg_pin4(const float* p) {
    float4 v;
    asm volatile("ld.global.nc.v4.f32 {%0,%1,%2,%3}, [%4];"
                 : "=f"(v.x), "=f"(v.y), "=f"(v.z), "=f"(v.w) : "l"(p));
    return v;
}

// ---------------------------------------------------------------------------
// Pass 1: moment reduction (lean regs, high occupancy).
// ---------------------------------------------------------------------------
__global__ void __launch_bounds__(RED_THREADS) reduce_kernel(const float4* __restrict__ X) {
    float s[9];
#pragma unroll
    for (int j = 0; j < 9; j++) s[j] = 0.f;

    const float4* base = X + (size_t)blockIdx.y * 3 * HW4;

#pragma unroll 2
    for (int p = blockIdx.x * RED_THREADS + threadIdx.x; p < HW4; p += RED_GX * RED_THREADS) {
        float4 x0 = base[p];
        float4 x1 = base[p + HW4];
        float4 x2 = base[p + 2 * HW4];

        s[0] += x0.x + x0.y + x0.z + x0.w;
        s[1] += x1.x + x1.y + x1.z + x1.w;
        s[2] += x2.x + x2.y + x2.z + x2.w;
        s[3] += x0.x*x0.x + x0.y*x0.y + x0.z*x0.z + x0.w*x0.w;
        s[4] += x0.x*x1.x + x0.y*x1.y + x0.z*x1.z + x0.w*x1.w;
        s[5] += x0.x*x2.x + x0.y*x2.y + x0.z*x2.z + x0.w*x2.w;
        s[6] += x1.x*x1.x + x1.y*x1.y + x1.z*x1.z + x1.w*x1.w;
        s[7] += x1.x*x2.x + x1.y*x2.y + x1.z*x2.z + x1.w*x2.w;
        s[8] += x2.x*x2.x + x2.y*x2.y + x2.z*x2.z + x2.w*x2.w;
    }

#pragma unroll
    for (int j = 0; j < 9; j++)
#pragma unroll
        for (int off = 16; off > 0; off >>= 1)
            s[j] += __shfl_down_sync(0xffffffffu, s[j], off);

    __shared__ float sh[RED_THREADS / 32][9];
    const int lane = threadIdx.x & 31;
    const int warp = threadIdx.x >> 5;
    if (lane == 0) {
#pragma unroll
        for (int j = 0; j < 9; j++) sh[warp][j] = s[j];
    }
    __syncthreads();
    if (threadIdx.x == 0) {
        float t[9];
#pragma unroll
        for (int j = 0; j < 9; j++) t[j] = 0.f;
        for (int w = 0; w < RED_THREADS / 32; w++)
#pragma unroll
            for (int j = 0; j < 9; j++) t[j] += sh[w][j];
        const int bid = blockIdx.y * RED_GX + blockIdx.x;
#pragma unroll
        for (int j = 0; j < 9; j++) g_partials[bid * 9 + j] = t[j];
    }
}

// ---------------------------------------------------------------------------
// Pass 2: fold the network into g_Ac[8][4] = {a0,a1,a2,c} per channel.
// ---------------------------------------------------------------------------
__global__ void finalize_kernel(
    const float* __restrict__ w1, const float* __restrict__ b1,
    const float* __restrict__ g2, const float* __restrict__ be2,
    const float* __restrict__ w3, const float* __restrict__ b3,
    const float* __restrict__ w4, const float* __restrict__ b4,
    const float* __restrict__ g5, const float* __restrict__ be5,
    const float* __restrict__ w6, const float* __restrict__ b6,
    const float* __restrict__ w7, const float* __restrict__ b7,
    const float* __restrict__ w8, const float* __restrict__ b8)
{
    __shared__ double sums[9];
    const int t = threadIdx.x;    // 288 threads = 9 warps
    const int warp = t >> 5;
    const int lane = t & 31;
    if (warp < 9) {
        double acc = 0.0;
        for (int i = lane; i < RED_BLOCKS; i += 32)
            acc += (double)g_partials[i * 9 + warp];
#pragma unroll
        for (int off = 16; off > 0; off >>= 1)
            acc += __shfl_down_sync(0xffffffffu, acc, off);
        if (lane == 0) sums[warp] = acc;
    }
    __syncthreads();
    if (t != 0) return;

    const double N = (double)BB * (double)HW;
    double m[3];
    for (int k = 0; k < 3; k++) m[k] = sums[k] / N;
    double E[3][3];
    E[0][0] = sums[3] / N; E[0][1] = E[1][0] = sums[4] / N; E[0][2] = E[2][0] = sums[5] / N;
    E[1][1] = sums[6] / N; E[1][2] = E[2][1] = sums[7] / N; E[2][2] = sums[8] / N;
    double Cov[3][3];
    for (int k = 0; k < 3; k++)
        for (int d = 0; d < 3; d++)
            Cov[k][d] = E[k][d] - m[k] * m[d];

    double M[8][3], c[8], Mn[8][3], cn[8];
    for (int r = 0; r < 3; r++) {
        for (int k = 0; k < 3; k++) M[r][k] = (double)w1[r * 3 + k];
        c[r] = (double)b1[r];
    }
    for (int r = 0; r < 3; r++) {               // BN2
        double mean = c[r];
        for (int k = 0; k < 3; k++) mean += M[r][k] * m[k];
        double var = 0.0;
        for (int k = 0; k < 3; k++)
            for (int d = 0; d < 3; d++)
                var += M[r][k] * Cov[k][d] * M[r][d];
        double sc = (double)g2[r] / sqrt(var + EPS);
        for (int k = 0; k < 3; k++) M[r][k] *= sc;
        c[r] = sc * (c[r] - mean) + (double)be2[r];
    }
    for (int o = 0; o < 8; o++) {               // conv w3 [8,3]
        for (int k = 0; k < 3; k++) {
            double a = 0.0;
            for (int r = 0; r < 3; r++) a += (double)w3[o * 3 + r] * M[r][k];
            Mn[o][k] = a;
        }
        double a = (double)b3[o];
        for (int r = 0; r < 3; r++) a += (double)w3[o * 3 + r] * c[r];
        cn[o] = a;
    }
    for (int o = 0; o < 8; o++) { for (int k = 0; k < 3; k++) M[o][k] = Mn[o][k]; c[o] = cn[o]; }
    for (int o = 0; o < 8; o++) {               // conv w4 [8,8]
        for (int k = 0; k < 3; k++) {
            double a = 0.0;
            for (int r = 0; r < 8; r++) a += (double)w4[o * 8 + r] * M[r][k];
            Mn[o][k] = a;
        }
        double a = (double)b4[o];
        for (int r = 0; r < 8; r++) a += (double)w4[o * 8 + r] * c[r];
        cn[o] = a;
    }
    for (int o = 0; o < 8; o++) { for (int k = 0; k < 3; k++) M[o][k] = Mn[o][k]; c[o] = cn[o]; }
    for (int o = 0; o < 8; o++) {               // BN5
        double mean = c[o];
        for (int k = 0; k < 3; k++) mean += M[o][k] * m[k];
        double var = 0.0;
        for (int k = 0; k < 3; k++)
            for (int d = 0; d < 3; d++)
                var += M[o][k] * Cov[k][d] * M[o][d];
        double sc = (double)g5[o] / sqrt(var + EPS);
        for (int k = 0; k < 3; k++) M[o][k] *= sc;
        c[o] = sc * (c[o] - mean) + (double)be5[o];
    }
    const float* Ws[3] = { w6, w7, w8 };
    const float* Bs[3] = { b6, b7, b8 };
    for (int L = 0; L < 3; L++) {
        const float* Wl = Ws[L];
        const float* Bl = Bs[L];
        for (int o = 0; o < 8; o++) {
            for (int k = 0; k < 3; k++) {
                double a = 0.0;
                for (int r = 0; r < 8; r++) a += (double)Wl[o * 8 + r] * M[r][k];
                Mn[o][k] = a;
            }
            double a = (double)Bl[o];
            for (int r = 0; r < 8; r++) a += (double)Wl[o * 8 + r] * c[r];
            cn[o] = a;
        }
        for (int o = 0; o < 8; o++) { for (int k = 0; k < 3; k++) M[o][k] = Mn[o][k]; c[o] = cn[o]; }
    }

    for (int o = 0; o < 8; o++) {
        g_Ac[o][0] = (float)M[o][0];
        g_Ac[o][1] = (float)M[o][1];
        g_Ac[o][2] = (float)M[o][2];
        g_Ac[o][3] = (float)c[o];
    }
}

// ---------------------------------------------------------------------------
// Pass 3: out = A x + c.  Coefficients fetched per-channel inside the o-loop
// via one un-hoistable LDG.128 (L1-resident) -> only 4 coef regs live at a
// time instead of 32 -> higher occupancy -> more memory ops in flight.
// ---------------------------------------------------------------------------
__global__ void __launch_bounds__(256) apply_kernel(const float4* __restrict__ X,
                                                    float4* __restrict__ OUT) {
    const int b  = (BB - 1) - blockIdx.y;            // reverse batch
    const int rb = (APL_GX - 1) - blockIdx.x;        // reverse pixel chunk
    const int p0 = rb * 1024 + threadIdx.x;

    const float4* base = X + (size_t)b * 3 * HW4;
    float4 x0[4], x1[4], x2[4];
#pragma unroll
    for (int q = 0; q < 4; q++) {
        const int p = p0 + q * 256;
        x0[q] = __ldcg(base + p);
        x1[q] = __ldcg(base + p + HW4);
        x2[q] = __ldcg(base + p + 2 * HW4);
    }

    float4* ob = OUT + (size_t)b * 8 * HW4;
#pragma unroll
    for (int o = 0; o < 8; o++) {
        const float4 k = ldg_pin4(&g_Ac[o][0]);      // a0,a1,a2,c
        float4* op = ob + o * HW4 + p0;
#pragma unroll
        for (int q = 0; q < 4; q++) {
            float4 r;
            r.x = fmaf(k.x, x0[q].x, fmaf(k.y, x1[q].x, fmaf(k.z, x2[q].x, k.w)));
            r.y = fmaf(k.x, x0[q].y, fmaf(k.y, x1[q].y, fmaf(k.z, x2[q].y, k.w)));
            r.z = fmaf(k.x, x0[q].z, fmaf(k.y, x1[q].z, fmaf(k.z, x2[q].z, k.w)));
            r.w = fmaf(k.x, x0[q].w, fmaf(k.y, x1[q].w, fmaf(k.z, x2[q].w, k.w)));
            __stcs(op + q * 256, r);
        }
    }
}

extern "C" void kernel_launch(void* const* d_in, const int* in_sizes, int n_in,
                              void* d_out, int out_size) {
    const float* x1  = (const float*)d_in[0];
    const float* w1  = (const float*)d_in[1];
    const float* b1  = (const float*)d_in[2];
    const float* g2  = (const float*)d_in[3];
    const float* be2 = (const float*)d_in[4];
    const float* w3  = (const float*)d_in[5];
    const float* b3  = (const float*)d_in[6];
    const float* w4  = (const float*)d_in[7];
    const float* b4  = (const float*)d_in[8];
    const float* g5  = (const float*)d_in[9];
    const float* be5 = (const float*)d_in[10];
    const float* w6  = (const float*)d_in[11];
    const float* b6  = (const float*)d_in[12];
    const float* w7  = (const float*)d_in[13];
    const float* b7  = (const float*)d_in[14];
    const float* w8  = (const float*)d_in[15];
    const float* b8  = (const float*)d_in[16];

    reduce_kernel<<<dim3(RED_GX, BB), RED_THREADS>>>((const float4*)x1);
    finalize_kernel<<<1, 288>>>(w1, b1, g2, be2, w3, b3, w4, b4,
                                g5, be5, w6, b6, w7, b7, w8, b8);
    apply_kernel<<<dim3(APL_GX, BB), 256>>>((const float4*)x1, (float4*)d_out);
}